// round 10
// baseline (speedup 1.0000x reference)
#include <cuda_runtime.h>

#define N0 1024
#define N1 512
#define I0 16
#define I1 64

// scratch (device globals: zero-initialized at load; the kernels maintain the
// invariant that ALL accumulator arrays are zero again after every
// kernel_launch call -- g_R0/g_R1 self-zeroed by finalize tiles, the small
// arrays zeroed by finalize's tail block after all readers finish).
__device__ float g_R0[N1 * N0];   // [j][a] : sum over i1 of X[j, i1, a]
__device__ float g_R1[N1 * N0];   // [j][a] : sum over i0 of X[i0, j, a]
__device__ float g_G [N1 * N0];   // [j][a] : X[j, j, a] (overwritten fully each call)
__device__ float g_S [N0];        // sum_j R0[j][a]
__device__ float g_D [N0];        // sum_j X[j,j,a]
__device__ float g_Rh0[N1];       // sum_a R0[j][a]
__device__ float g_Rh1[N1];       // sum_a R1[j][a]
__device__ float g_Gh [N1];       // sum_a X[j,j,a]
__device__ float g_scal[2];       // { sum_a S, sum_a D }
__device__ unsigned int g_cnt_main;
__device__ unsigned int g_cnt_fin;

__device__ __forceinline__ void red4(float* addr, float4 v) {
    asm volatile("red.global.add.v4.f32 [%0], {%1, %2, %3, %4};"
                 :: "l"(addr), "f"(v.x), "f"(v.y), "f"(v.z), "f"(v.w)
                 : "memory");
}

__device__ __forceinline__ float ldcg(const float* p) {
    float v;
    asm volatile("ld.global.cg.f32 %0, [%1];" : "=f"(v) : "l"(p));
    return v;
}

__device__ __forceinline__ float warp_sum(float v) {
    #pragma unroll
    for (int o = 16; o > 0; o >>= 1) v += __shfl_down_sync(0xffffffffu, v, o);
    return v;
}

// Single streaming pass over X (1 GiB), geometry = measured best (162.7us):
// 16 i0 x 64 i1 x half-a, 128 threads, occ 4, 512 blocks.
// Fused side-reductions (all from values already in registers):
//   red4 -> g_R1 per t, g_R0 per k, g_S (block total), g_D (diag blocks)
//   warp-shfl + scalar atomicAdd -> g_Rh1 per t, g_Rh0 per k, g_Gh (diag)
// The LAST block (counter) computes g_scal from g_Rh0/g_Gh. This removes the
// reduce_j kernel entirely.
__global__ __launch_bounds__(128, 4) void main_pass(const float* __restrict__ X) {
    const int i0base = blockIdx.x * I0;                 // 32 groups
    const int i1base = blockIdx.y * I1;                 // 8 groups
    const int tx = threadIdx.x;
    const int ax = blockIdx.z * 128 + tx;               // float4 lane (0..255)
    const int lane = tx & 31;
    const float4* __restrict__ Xv = reinterpret_cast<const float4*>(X);

    // Diagonal gather (one block per i0-group per z-half: by == bx % 8).
    // Overlapped with the stream; feeds g_G, g_D, g_Gh.
    if ((int)blockIdx.y == (blockIdx.x & 7)) {
        float4 dacc = make_float4(0.f, 0.f, 0.f, 0.f);
        #pragma unroll
        for (int k = 0; k < I0; k++) {
            const int d = i0base + k;
            const float4 v = __ldg(Xv + (size_t)(d * N1 + d) * (N0 / 4) + ax);
            *reinterpret_cast<float4*>(&g_G[(size_t)d * N0 + ax * 4]) = v;
            dacc.x += v.x; dacc.y += v.y; dacc.z += v.z; dacc.w += v.w;
            const float gs = warp_sum(v.x + v.y + v.z + v.w);
            if (lane == 0) atomicAdd(&g_Gh[d], gs);
        }
        red4(&g_D[ax * 4], dacc);
    }

    float4 r0acc[I0];
    #pragma unroll
    for (int k = 0; k < I0; k++) r0acc[k] = make_float4(0.f, 0.f, 0.f, 0.f);

    for (int t = 0; t < I1; t++) {
        const int i1 = i1base + t;
        float4 r1 = make_float4(0.f, 0.f, 0.f, 0.f);
        #pragma unroll
        for (int k = 0; k < I0; k++) {
            const float4 v = __ldcs(Xv + (size_t)((i0base + k) * N1 + i1) * (N0 / 4) + ax);
            r0acc[k].x += v.x; r0acc[k].y += v.y; r0acc[k].z += v.z; r0acc[k].w += v.w;
            r1.x += v.x; r1.y += v.y; r1.z += v.z; r1.w += v.w;
        }
        red4(&g_R1[(size_t)i1 * N0 + ax * 4], r1);
        const float s1 = warp_sum(r1.x + r1.y + r1.z + r1.w);
        if (lane == 0) atomicAdd(&g_Rh1[i1], s1);
    }

    float4 sacc = make_float4(0.f, 0.f, 0.f, 0.f);
    #pragma unroll
    for (int k = 0; k < I0; k++) {
        red4(&g_R0[(size_t)(i0base + k) * N0 + ax * 4], r0acc[k]);
        sacc.x += r0acc[k].x; sacc.y += r0acc[k].y;
        sacc.z += r0acc[k].z; sacc.w += r0acc[k].w;
        const float s0 = warp_sum(r0acc[k].x + r0acc[k].y + r0acc[k].z + r0acc[k].w);
        if (lane == 0) atomicAdd(&g_Rh0[i0base + k], s0);
    }
    red4(&g_S[ax * 4], sacc);

    // Tail block: once every block's atomics are visible, derive the scalars.
    __threadfence();
    __syncthreads();
    __shared__ unsigned int s_last;
    if (tx == 0) s_last = (atomicAdd(&g_cnt_main, 1u) == 511u) ? 1u : 0u;
    __syncthreads();
    if (s_last) {
        if (tx == 0) g_cnt_main = 0;
        float s0 = 0.f, s1 = 0.f;
        #pragma unroll
        for (int r = 0; r < 4; r++) {
            const int j = tx + r * 128;
            s0 += ldcg(&g_Rh0[j]);
            s1 += ldcg(&g_Gh[j]);
        }
        s0 = warp_sum(s0);
        s1 = warp_sum(s1);
        __shared__ float sm[2][4];
        if (lane == 0) { sm[0][tx >> 5] = s0; sm[1][tx >> 5] = s1; }
        __syncthreads();
        if (tx == 0) {
            g_scal[0] = sm[0][0] + sm[0][1] + sm[0][2] + sm[0][3];   // sum_a S
            g_scal[1] = sm[1][0] + sm[1][1] + sm[1][2] + sm[1][3];   // sum_a D
        }
    }
}

// Transposing finalize: scratch is [j][a], output is Y[a][j].
// 32x32 tiles through smem for coalesced loads AND stores. Each R0/R1
// element is read by exactly one block; the loading thread re-zeros it
// right after the load (race-free). The LAST finalize block (counter)
// zeroes the small accumulator arrays after all readers have finished,
// restoring the all-zeros invariant for the next kernel_launch/replay.
__global__ void finalize(const float* __restrict__ w, float* __restrict__ Y) {
    __shared__ float t0[32][33], t1[32][33], tg[32][33];
    const int at = blockIdx.x * 32;   // a tile (32 tiles)
    const int jt = blockIdx.y * 32;   // j tile (16 tiles)
    const int tx = threadIdx.x;       // 0..31
    const int ty = threadIdx.y;       // 0..7
    const int tid = ty * 32 + tx;     // 0..255

    #pragma unroll
    for (int r = 0; r < 4; r++) {
        const int jl = ty + r * 8;
        const size_t base = (size_t)(jt + jl) * N0 + at + tx;
        t0[jl][tx] = g_R0[base];
        t1[jl][tx] = g_R1[base];
        tg[jl][tx] = g_G [base];
        g_R0[base] = 0.f;
        g_R1[base] = 0.f;
    }
    __syncthreads();

    const float w0 = w[0], w1 = w[1], w2 = w[2], w3 = w[3], w4 = w[4];
    const float w5 = w[5], w6 = w[6], w7 = w[7], w8 = w[8], w9 = w[9];
    const float c  = w5 * g_scal[0] + w6 * g_scal[1];
    const int   j  = jt + tx;
    const float cj = c + w7 * g_Rh0[j] + w8 * g_Rh1[j] + w9 * g_Gh[j];

    #pragma unroll
    for (int r = 0; r < 4; r++) {
        const int al = ty + r * 8;
        const int a  = at + al;
        const float val = cj + w0 * g_S[a] + w1 * g_D[a]
                        + w2 * t0[tx][al] + w3 * t1[tx][al] + w4 * tg[tx][al];
        Y[(size_t)a * N1 + j] = val;
    }

    // Tail block: zero the small accumulators after every block is done.
    __threadfence();
    __syncthreads();
    __shared__ unsigned int s_last;
    if (tid == 0) s_last = (atomicAdd(&g_cnt_fin, 1u) == 511u) ? 1u : 0u;
    __syncthreads();
    if (s_last) {
        if (tid < 2) { g_scal[tid] = 0.f; }
        if (tid == 0) g_cnt_fin = 0;
        #pragma unroll
        for (int r = 0; r < 4; r++) {
            const int i = tid + r * 256;
            g_S[i] = 0.f;
            g_D[i] = 0.f;
        }
        #pragma unroll
        for (int r = 0; r < 2; r++) {
            const int i = tid + r * 256;
            g_Rh0[i] = 0.f;
            g_Rh1[i] = 0.f;
            g_Gh [i] = 0.f;
        }
    }
}

extern "C" void kernel_launch(void* const* d_in, const int* in_sizes, int n_in,
                              void* d_out, int out_size) {
    const float* X = (const float*)d_in[0];   // (512, 512, 1024) fp32
    const float* w = (const float*)d_in[1];   // (10, 1, 1) fp32
    float* Y = (float*)d_out;                 // (1024, 512) fp32

    main_pass<<<dim3(N1 / I0, N1 / I1, 2), 128>>>(X);
    finalize<<<dim3(N0 / 32, N1 / 32), dim3(32, 8)>>>(w, Y);
}

// round 11
// speedup vs baseline: 1.0076x; 1.0076x over previous
#include <cuda_runtime.h>

#define N0 1024
#define N1 512
#define I0 16
#define I1 64

// scratch (device globals: zero-initialized at load; the kernels maintain the
// invariant that ALL accumulator arrays are zero again after every
// kernel_launch call -- g_R0/g_R1 self-zeroed by finalize tiles, the small
// arrays zeroed by the trailing cleanup micro-kernel).
__device__ float g_R0[N1 * N0];   // [j][a] : sum over i1 of X[j, i1, a]
__device__ float g_R1[N1 * N0];   // [j][a] : sum over i0 of X[i0, j, a]
__device__ float g_G [N1 * N0];   // [j][a] : X[j, j, a] (overwritten fully each call)
__device__ float g_S [N0];        // sum_j R0[j][a]
__device__ float g_D [N0];        // sum_j X[j,j,a]
__device__ float g_Rh0[N1];       // sum_a R0[j][a]
__device__ float g_Rh1[N1];       // sum_a R1[j][a]
__device__ float g_Gh [N1];       // sum_a X[j,j,a]
__device__ float g_scal[2];       // { sum_a S, sum_a D }
__device__ unsigned int g_cnt_main;

__device__ __forceinline__ void red4(float* addr, float4 v) {
    asm volatile("red.global.add.v4.f32 [%0], {%1, %2, %3, %4};"
                 :: "l"(addr), "f"(v.x), "f"(v.y), "f"(v.z), "f"(v.w)
                 : "memory");
}

__device__ __forceinline__ float ldcg(const float* p) {
    float v;
    asm volatile("ld.global.cg.f32 %0, [%1];" : "=f"(v) : "l"(p));
    return v;
}

__device__ __forceinline__ float warp_sum(float v) {
    #pragma unroll
    for (int o = 16; o > 0; o >>= 1) v += __shfl_down_sync(0xffffffffu, v, o);
    return v;
}

// Single streaming pass over X (1 GiB): 16 i0 x 64 i1 x half-a, 128 threads,
// occ 4, 512 blocks. All of reduce_j's work is fused in (R10 measured this
// at ~159-160us, faster than any unfused main):
//   red4 -> g_R1 per t, g_R0 per k, g_S (block total), g_D (diag blocks)
//   warp-shfl + scalar atomicAdd -> g_Rh1 per t, g_Rh0 per k, g_Gh (diag)
// The LAST block (counter) computes g_scal from g_Rh0/g_Gh.
__global__ __launch_bounds__(128, 4) void main_pass(const float* __restrict__ X) {
    const int i0base = blockIdx.x * I0;                 // 32 groups
    const int i1base = blockIdx.y * I1;                 // 8 groups
    const int tx = threadIdx.x;
    const int ax = blockIdx.z * 128 + tx;               // float4 lane (0..255)
    const int lane = tx & 31;
    const float4* __restrict__ Xv = reinterpret_cast<const float4*>(X);

    // Diagonal gather (one block per i0-group per z-half: by == bx % 8).
    // Overlapped with the stream; feeds g_G, g_D, g_Gh.
    if ((int)blockIdx.y == (blockIdx.x & 7)) {
        float4 dacc = make_float4(0.f, 0.f, 0.f, 0.f);
        #pragma unroll
        for (int k = 0; k < I0; k++) {
            const int d = i0base + k;
            const float4 v = __ldg(Xv + (size_t)(d * N1 + d) * (N0 / 4) + ax);
            *reinterpret_cast<float4*>(&g_G[(size_t)d * N0 + ax * 4]) = v;
            dacc.x += v.x; dacc.y += v.y; dacc.z += v.z; dacc.w += v.w;
            const float gs = warp_sum(v.x + v.y + v.z + v.w);
            if (lane == 0) atomicAdd(&g_Gh[d], gs);
        }
        red4(&g_D[ax * 4], dacc);
    }

    float4 r0acc[I0];
    #pragma unroll
    for (int k = 0; k < I0; k++) r0acc[k] = make_float4(0.f, 0.f, 0.f, 0.f);

    for (int t = 0; t < I1; t++) {
        const int i1 = i1base + t;
        float4 r1 = make_float4(0.f, 0.f, 0.f, 0.f);
        #pragma unroll
        for (int k = 0; k < I0; k++) {
            const float4 v = __ldcs(Xv + (size_t)((i0base + k) * N1 + i1) * (N0 / 4) + ax);
            r0acc[k].x += v.x; r0acc[k].y += v.y; r0acc[k].z += v.z; r0acc[k].w += v.w;
            r1.x += v.x; r1.y += v.y; r1.z += v.z; r1.w += v.w;
        }
        red4(&g_R1[(size_t)i1 * N0 + ax * 4], r1);
        const float s1 = warp_sum(r1.x + r1.y + r1.z + r1.w);
        if (lane == 0) atomicAdd(&g_Rh1[i1], s1);
    }

    float4 sacc = make_float4(0.f, 0.f, 0.f, 0.f);
    #pragma unroll
    for (int k = 0; k < I0; k++) {
        red4(&g_R0[(size_t)(i0base + k) * N0 + ax * 4], r0acc[k]);
        sacc.x += r0acc[k].x; sacc.y += r0acc[k].y;
        sacc.z += r0acc[k].z; sacc.w += r0acc[k].w;
        const float s0 = warp_sum(r0acc[k].x + r0acc[k].y + r0acc[k].z + r0acc[k].w);
        if (lane == 0) atomicAdd(&g_Rh0[i0base + k], s0);
    }
    red4(&g_S[ax * 4], sacc);

    // Tail block: once every block's atomics are visible, derive the scalars.
    __threadfence();
    __syncthreads();
    __shared__ unsigned int s_last;
    if (tx == 0) s_last = (atomicAdd(&g_cnt_main, 1u) == 511u) ? 1u : 0u;
    __syncthreads();
    if (s_last) {
        if (tx == 0) g_cnt_main = 0;
        float s0 = 0.f, s1 = 0.f;
        #pragma unroll
        for (int r = 0; r < 4; r++) {
            const int j = tx + r * 128;
            s0 += ldcg(&g_Rh0[j]);
            s1 += ldcg(&g_Gh[j]);
        }
        s0 = warp_sum(s0);
        s1 = warp_sum(s1);
        __shared__ float sm[2][4];
        if (lane == 0) { sm[0][tx >> 5] = s0; sm[1][tx >> 5] = s1; }
        __syncthreads();
        if (tx == 0) {
            g_scal[0] = sm[0][0] + sm[0][1] + sm[0][2] + sm[0][3];   // sum_a S
            g_scal[1] = sm[1][0] + sm[1][1] + sm[1][2] + sm[1][3];   // sum_a D
        }
    }
}

// Transposing finalize: scratch is [j][a], output is Y[a][j].
// 32x32 tiles through smem for coalesced loads AND stores. Each R0/R1
// element is read by exactly one block; the loading thread re-zeros it
// right after the load (race-free). Pure hot path — no fences, no counters
// (the R10 tail-block version cost +11us from gpu-scope threadfences).
__global__ void finalize(const float* __restrict__ w, float* __restrict__ Y) {
    __shared__ float t0[32][33], t1[32][33], tg[32][33];
    const int at = blockIdx.x * 32;   // a tile (32 tiles)
    const int jt = blockIdx.y * 32;   // j tile (16 tiles)
    const int tx = threadIdx.x;       // 0..31
    const int ty = threadIdx.y;       // 0..7

    #pragma unroll
    for (int r = 0; r < 4; r++) {
        const int jl = ty + r * 8;
        const size_t base = (size_t)(jt + jl) * N0 + at + tx;
        t0[jl][tx] = g_R0[base];
        t1[jl][tx] = g_R1[base];
        tg[jl][tx] = g_G [base];
        g_R0[base] = 0.f;
        g_R1[base] = 0.f;
    }
    __syncthreads();

    const float w0 = w[0], w1 = w[1], w2 = w[2], w3 = w[3], w4 = w[4];
    const float w5 = w[5], w6 = w[6], w7 = w[7], w8 = w[8], w9 = w[9];
    const float c  = w5 * g_scal[0] + w6 * g_scal[1];
    const int   j  = jt + tx;
    const float cj = c + w7 * g_Rh0[j] + w8 * g_Rh1[j] + w9 * g_Gh[j];

    #pragma unroll
    for (int r = 0; r < 4; r++) {
        const int al = ty + r * 8;
        const int a  = at + al;
        const float val = cj + w0 * g_S[a] + w1 * g_D[a]
                        + w2 * t0[tx][al] + w3 * t1[tx][al] + w4 * tg[tx][al];
        Y[(size_t)a * N1 + j] = val;
    }
}

// Micro cleanup: restore the zero invariant on the small accumulators
// (10 KB) after finalize has consumed them. One block, trivial.
__global__ void cleanup() {
    const int tid = threadIdx.x;   // 0..255
    #pragma unroll
    for (int r = 0; r < 4; r++) {
        const int i = tid + r * 256;
        g_S[i] = 0.f;
        g_D[i] = 0.f;
    }
    #pragma unroll
    for (int r = 0; r < 2; r++) {
        const int i = tid + r * 256;
        g_Rh0[i] = 0.f;
        g_Rh1[i] = 0.f;
        g_Gh [i] = 0.f;
    }
    if (tid < 2) g_scal[tid] = 0.f;
}

extern "C" void kernel_launch(void* const* d_in, const int* in_sizes, int n_in,
                              void* d_out, int out_size) {
    const float* X = (const float*)d_in[0];   // (512, 512, 1024) fp32
    const float* w = (const float*)d_in[1];   // (10, 1, 1) fp32
    float* Y = (float*)d_out;                 // (1024, 512) fp32

    main_pass<<<dim3(N1 / I0, N1 / I1, 2), 128>>>(X);
    finalize<<<dim3(N0 / 32, N1 / 32), dim3(32, 8)>>>(w, Y);
    cleanup<<<1, 256>>>();
}